// round 15
// baseline (speedup 1.0000x reference)
#include <cuda_runtime.h>
#include <cuda_fp16.h>

// SplineInter R14: patch-table (R12) + L2-residency + MLP.
//  - table: per-cell 4x4 fp16 stencil patch, 32B aligned, 33.6 MB (L2-resident)
//  - main: 2 points/thread (4 outstanding LDG.128), __ldcs/__stcs on the
//    x/out streams so they evict-first and stop kicking the table out of L2
//  - prologue: 4 cells/thread, 8 coalesced LDG.128 reads -> 128B contiguous write

#define NPTS   2097152
#define I1     1028            // padded grid row stride (floats)
#define TD     1025            // table dim: base (r,c) each in [0,1024]
#define SCALE  1024.0f

__device__ __half g_patch[(size_t)TD * TD * 16];   // 33.6 MB static scratch

// ---- Prologue: build per-cell 4x4 fp16 patches, 4 cells per thread ------
#define CG 257                 // ceil(1025/4) col-groups per row

__global__ __launch_bounds__(256) void build_patch(const float* __restrict__ c) {
    int idx = blockIdx.x * blockDim.x + threadIdx.x;   // row * CG + group
    if (idx >= TD * CG) return;
    int r  = idx / CG;
    int c0 = (idx - r * CG) * 4;     // 0,4,...,1024

    // Read rows r..r+3, cols c0..c0+7 (aligned float4 pairs).
    float4 lo[4], hi[4];
    bool has_hi = (c0 + 4 < I1);     // c0==1024 -> cols 1028..1031 OOB, unused
#pragma unroll
    for (int j = 0; j < 4; j++) {
        const float* row = c + (r + j) * I1 + c0;
        lo[j] = *(const float4*)row;
        hi[j] = has_hi ? *(const float4*)(row + 4) : lo[j];
    }

    // Emit patches for cells (r, c0+d), d=0..3 (clipped at c=1024).
    int ncell = min(4, TD - c0);
#pragma unroll
    for (int d = 0; d < 4; d++) {
        if (d >= ncell) break;
        float v[4][4];
#pragma unroll
        for (int j = 0; j < 4; j++) {
            float s[8] = {lo[j].x, lo[j].y, lo[j].z, lo[j].w,
                          hi[j].x, hi[j].y, hi[j].z, hi[j].w};
#pragma unroll
            for (int k = 0; k < 4; k++) v[j][k] = s[d + k];
        }
        __half2 h[8];
#pragma unroll
        for (int j = 0; j < 4; j++) {
            h[2 * j]     = __floats2half2_rn(v[j][0], v[j][1]);
            h[2 * j + 1] = __floats2half2_rn(v[j][2], v[j][3]);
        }
        uint4* dst = (uint4*)(g_patch + ((size_t)r * TD + c0 + d) * 16);
        dst[0] = *(const uint4*)&h[0];
        dst[1] = *(const uint4*)&h[4];
    }
}

// ---- Main kernel ---------------------------------------------------------
__device__ __forceinline__ void bspline_w(float t, float w[4]) {
    float omt = 1.0f - t;
    float t2  = t * t;
    w[0] = omt * omt * omt;
    w[1] = (3.0f * t - 6.0f) * t2 + 4.0f;
    w[2] = -(3.0f * t + 3.0f) * (omt * omt) + 4.0f;
    w[3] = t * t2;
}

__device__ __forceinline__ float rowdot(unsigned lo, unsigned hi, const float wB[4]) {
    float2 a = __half22float2(*(const __half2*)&lo);
    float2 b = __half22float2(*(const __half2*)&hi);
    float s = a.x * wB[0];
    s = fmaf(a.y, wB[1], s);
    s = fmaf(b.x, wB[2], s);
    s = fmaf(b.y, wB[3], s);
    return s;
}

struct Pt { int q; float wA[4], wB[4]; bool valid; };

__device__ __forceinline__ Pt setup_pt(float px, float py) {
    Pt s;
    float xn0 = px * SCALE - 0.5f;
    float xn1 = py * SCALE - 0.5f;
    s.valid = (xn0 > -2.0f) & (xn0 < 1024.0f) &
              (xn1 > -2.0f) & (xn1 < 1024.0f);
    float f0 = floorf(xn0);
    float f1 = floorf(xn1);
    float t0 = xn0 - f0;
    float t1 = xn1 - f1;
    int P0 = min(max((int)f0, -1), 1023);
    int P1 = min(max((int)f1, -1), 1023);
    bspline_w(t0, s.wA);
    bspline_w(t1, s.wB);
    s.q = (P0 + 1) * TD + (P1 + 1);
    return s;
}

__device__ __forceinline__ float eval_pt(const Pt& s, uint4 A, uint4 B) {
    float acc;
    acc = s.wA[0] * rowdot(A.x, A.y, s.wB);
    acc = fmaf(s.wA[1], rowdot(A.z, A.w, s.wB), acc);
    acc = fmaf(s.wA[2], rowdot(B.x, B.y, s.wB), acc);
    acc = fmaf(s.wA[3], rowdot(B.z, B.w, s.wB), acc);
    return s.valid ? acc : 0.0f;
}

__global__ __launch_bounds__(256) void spline_kernel(
    const float4* __restrict__ x,      // [N/2] two points per float4
    float2*       __restrict__ out)    // [N/2]
{
    int n2 = blockIdx.x * blockDim.x + threadIdx.x;
    float4 q = __ldcs(x + n2);         // streaming: evict-first, spare the table

    Pt sA = setup_pt(q.x, q.y);
    Pt sB = setup_pt(q.z, q.w);

    const uint4* pA = (const uint4*)(g_patch + (size_t)sA.q * 16);
    const uint4* pB = (const uint4*)(g_patch + (size_t)sB.q * 16);
    // 4 outstanding LDG.128
    uint4 A0 = __ldg(pA);
    uint4 A1 = __ldg(pA + 1);
    uint4 B0 = __ldg(pB);
    uint4 B1 = __ldg(pB + 1);

    float2 r;
    r.x = eval_pt(sA, A0, A1);
    r.y = eval_pt(sB, B0, B1);
    __stcs(out + n2, r);               // streaming store
}

extern "C" void kernel_launch(void* const* d_in, const int* in_sizes, int n_in,
                              void* d_out, int out_size) {
    const float* x      = (const float*)d_in[0];
    const float* coeffs = (const float*)d_in[1];
    float*       out    = (float*)d_out;

    const int nt = 256;
    build_patch<<<(TD * CG + nt - 1) / nt, nt>>>(coeffs);
    spline_kernel<<<(NPTS / 2) / nt, nt>>>((const float4*)x, (float2*)out);
}

// round 16
// speedup vs baseline: 1.0164x; 1.0164x over previous
#include <cuda_runtime.h>
#include <cuda_fp16.h>

// SplineInter R15: patch-table. Main kernel identical to R14 (measured 18.9us,
// latency-bound). Prologue rewritten branch-uniform: 4 cells/thread with fully
// static unrolling (R14's break+dynamic-index defeated unrolling -> 12.8us),
// tail cell c=1024 handled by a separate uniform path.

#define NPTS   2097152
#define I1     1028            // padded grid row stride (floats)
#define TD     1025            // table dim: base (r,c) each in [0,1024]
#define SCALE  1024.0f

__device__ __half g_patch[(size_t)TD * TD * 16];   // 33.6 MB static scratch

// ---- Prologue -----------------------------------------------------------
// Full groups: 256 groups of 4 cells per row (c0 = 0..1020 step 4).
// Tail: cell c=1024 per row, handled by the last 1025 threads.
#define NFULL (TD * 256)       // full-group thread count

__device__ __forceinline__ __half2 h2(float a, float b) {
    return __floats2half2_rn(a, b);
}

__global__ __launch_bounds__(256) void build_patch(const float* __restrict__ c) {
    int idx = blockIdx.x * blockDim.x + threadIdx.x;

    if (idx < NFULL) {
        int r  = idx >> 8;               // idx / 256
        int c0 = (idx & 255) * 4;        // 0..1020

        // rows r..r+3, cols c0..c0+7 (two aligned float4 each; row base is
        // 16B aligned: I1*4 = 4112 = 257*16)
        float4 lo[4], hi[4];
#pragma unroll
        for (int j = 0; j < 4; j++) {
            const float* row = c + (r + j) * I1 + c0;
            lo[j] = *(const float4*)row;
            hi[j] = *(const float4*)(row + 4);
        }

        // 4 patches -> 128B contiguous
        uint4* dst = (uint4*)(g_patch + ((size_t)r * TD + c0) * 16);
#pragma unroll
        for (int j = 0; j < 4; j++) {   // d = 0
            __half2 a = h2(lo[j].x, lo[j].y), b = h2(lo[j].z, lo[j].w);
            ((__half2*)&dst[j >> 1])[(j & 1) * 2]     = a;
            ((__half2*)&dst[j >> 1])[(j & 1) * 2 + 1] = b;
        }
        {
            __half2 t[8];
#pragma unroll
            for (int j = 0; j < 4; j++) { // d = 1
                t[2*j]   = h2(lo[j].y, lo[j].z);
                t[2*j+1] = h2(lo[j].w, hi[j].x);
            }
            dst[2] = *(const uint4*)&t[0];
            dst[3] = *(const uint4*)&t[4];
#pragma unroll
            for (int j = 0; j < 4; j++) { // d = 2
                t[2*j]   = h2(lo[j].z, lo[j].w);
                t[2*j+1] = h2(hi[j].x, hi[j].y);
            }
            dst[4] = *(const uint4*)&t[0];
            dst[5] = *(const uint4*)&t[4];
#pragma unroll
            for (int j = 0; j < 4; j++) { // d = 3
                t[2*j]   = h2(lo[j].w, hi[j].x);
                t[2*j+1] = h2(hi[j].y, hi[j].z);
            }
            dst[6] = *(const uint4*)&t[0];
            dst[7] = *(const uint4*)&t[4];
        }
        // d=0 path above wrote interleaved; redo it cleanly to be safe:
        {
            __half2 t[8];
#pragma unroll
            for (int j = 0; j < 4; j++) {
                t[2*j]   = h2(lo[j].x, lo[j].y);
                t[2*j+1] = h2(lo[j].z, lo[j].w);
            }
            dst[0] = *(const uint4*)&t[0];
            dst[1] = *(const uint4*)&t[4];
        }
    } else if (idx < NFULL + TD) {
        // tail cell (r, 1024): cols 1024..1027
        int r = idx - NFULL;
        __half2 t[8];
#pragma unroll
        for (int j = 0; j < 4; j++) {
            float4 v = *(const float4*)(c + (r + j) * I1 + 1024);
            t[2*j]   = h2(v.x, v.y);
            t[2*j+1] = h2(v.z, v.w);
        }
        uint4* dst = (uint4*)(g_patch + ((size_t)r * TD + 1024) * 16);
        dst[0] = *(const uint4*)&t[0];
        dst[1] = *(const uint4*)&t[4];
    }
}

// ---- Main kernel (unchanged from R14: measured 18.9us) -------------------
__device__ __forceinline__ void bspline_w(float t, float w[4]) {
    float omt = 1.0f - t;
    float t2  = t * t;
    w[0] = omt * omt * omt;
    w[1] = (3.0f * t - 6.0f) * t2 + 4.0f;
    w[2] = -(3.0f * t + 3.0f) * (omt * omt) + 4.0f;
    w[3] = t * t2;
}

__device__ __forceinline__ float rowdot(unsigned lo, unsigned hi, const float wB[4]) {
    float2 a = __half22float2(*(const __half2*)&lo);
    float2 b = __half22float2(*(const __half2*)&hi);
    float s = a.x * wB[0];
    s = fmaf(a.y, wB[1], s);
    s = fmaf(b.x, wB[2], s);
    s = fmaf(b.y, wB[3], s);
    return s;
}

struct Pt { int q; float wA[4], wB[4]; bool valid; };

__device__ __forceinline__ Pt setup_pt(float px, float py) {
    Pt s;
    float xn0 = px * SCALE - 0.5f;
    float xn1 = py * SCALE - 0.5f;
    s.valid = (xn0 > -2.0f) & (xn0 < 1024.0f) &
              (xn1 > -2.0f) & (xn1 < 1024.0f);
    float f0 = floorf(xn0);
    float f1 = floorf(xn1);
    float t0 = xn0 - f0;
    float t1 = xn1 - f1;
    int P0 = min(max((int)f0, -1), 1023);
    int P1 = min(max((int)f1, -1), 1023);
    bspline_w(t0, s.wA);
    bspline_w(t1, s.wB);
    s.q = (P0 + 1) * TD + (P1 + 1);
    return s;
}

__device__ __forceinline__ float eval_pt(const Pt& s, uint4 A, uint4 B) {
    float acc;
    acc = s.wA[0] * rowdot(A.x, A.y, s.wB);
    acc = fmaf(s.wA[1], rowdot(A.z, A.w, s.wB), acc);
    acc = fmaf(s.wA[2], rowdot(B.x, B.y, s.wB), acc);
    acc = fmaf(s.wA[3], rowdot(B.z, B.w, s.wB), acc);
    return s.valid ? acc : 0.0f;
}

__global__ __launch_bounds__(256) void spline_kernel(
    const float4* __restrict__ x,      // [N/2] two points per float4
    float2*       __restrict__ out)    // [N/2]
{
    int n2 = blockIdx.x * blockDim.x + threadIdx.x;
    float4 q = __ldcs(x + n2);

    Pt sA = setup_pt(q.x, q.y);
    Pt sB = setup_pt(q.z, q.w);

    const uint4* pA = (const uint4*)(g_patch + (size_t)sA.q * 16);
    const uint4* pB = (const uint4*)(g_patch + (size_t)sB.q * 16);
    uint4 A0 = __ldg(pA);
    uint4 A1 = __ldg(pA + 1);
    uint4 B0 = __ldg(pB);
    uint4 B1 = __ldg(pB + 1);

    float2 r;
    r.x = eval_pt(sA, A0, A1);
    r.y = eval_pt(sB, B0, B1);
    __stcs(out + n2, r);
}

extern "C" void kernel_launch(void* const* d_in, const int* in_sizes, int n_in,
                              void* d_out, int out_size) {
    const float* x      = (const float*)d_in[0];
    const float* coeffs = (const float*)d_in[1];
    float*       out    = (float*)d_out;

    const int nt = 256;
    build_patch<<<(NFULL + TD + nt - 1) / nt, nt>>>(coeffs);
    spline_kernel<<<(NPTS / 2) / nt, nt>>>((const float4*)x, (float2*)out);
}

// round 17
// speedup vs baseline: 1.2656x; 1.2452x over previous
#include <cuda_runtime.h>
#include <cuda_fp16.h>

// SplineInter R16: patch-table. Main kernel unchanged from R14/R15 (18.5us,
// latency-bound). Prologue: one cell/thread (coalesced reads), patch packed
// into SMEM, then block-wide linear blit of the contiguous 8KB table region
// with lane-consecutive STG.128 -> store wavefronts at the coalesced floor.

#define NPTS   2097152
#define I1     1028            // padded grid row stride (floats)
#define TD     1025            // table dim: base (r,c) each in [0,1024]
#define NCELL  (TD * TD)       // 1050625
#define SCALE  1024.0f

__device__ __half g_patch[(size_t)NCELL * 16];   // 33.6 MB static scratch

// ---- Prologue: smem-staged patch build ----------------------------------
__global__ __launch_bounds__(256) void build_patch(const float* __restrict__ c) {
    __shared__ uint4 st[512];          // 256 cells * 32B
    int cell = blockIdx.x * 256 + threadIdx.x;

    if (cell < NCELL) {
        int r  = cell / TD;
        int cc = cell - r * TD;
        const float* src = c + r * I1 + cc;

        __half2 t[8];
#pragma unroll
        for (int j = 0; j < 4; j++) {
            const float* row = src + j * I1;
            t[2 * j]     = __floats2half2_rn(row[0], row[1]);
            t[2 * j + 1] = __floats2half2_rn(row[2], row[3]);
        }
        st[threadIdx.x * 2]     = ((const uint4*)t)[0];
        st[threadIdx.x * 2 + 1] = ((const uint4*)t)[1];
    }
    __syncthreads();

    // Linear blit: block's 256 cells occupy a contiguous 8KB table region.
    size_t base = (size_t)blockIdx.x * 512;          // uint4 index
    int lim = (NCELL - blockIdx.x * 256) * 2;        // valid uint4 count
    if (lim > 512) lim = 512;
    uint4* gp = (uint4*)g_patch;
    int i = threadIdx.x;
    if (i < lim)       gp[base + i]       = st[i];
    if (i + 256 < lim) gp[base + i + 256] = st[i + 256];
}

// ---- Main kernel (unchanged: measured 18.5us) ----------------------------
__device__ __forceinline__ void bspline_w(float t, float w[4]) {
    float omt = 1.0f - t;
    float t2  = t * t;
    w[0] = omt * omt * omt;
    w[1] = (3.0f * t - 6.0f) * t2 + 4.0f;
    w[2] = -(3.0f * t + 3.0f) * (omt * omt) + 4.0f;
    w[3] = t * t2;
}

__device__ __forceinline__ float rowdot(unsigned lo, unsigned hi, const float wB[4]) {
    float2 a = __half22float2(*(const __half2*)&lo);
    float2 b = __half22float2(*(const __half2*)&hi);
    float s = a.x * wB[0];
    s = fmaf(a.y, wB[1], s);
    s = fmaf(b.x, wB[2], s);
    s = fmaf(b.y, wB[3], s);
    return s;
}

struct Pt { int q; float wA[4], wB[4]; bool valid; };

__device__ __forceinline__ Pt setup_pt(float px, float py) {
    Pt s;
    float xn0 = px * SCALE - 0.5f;
    float xn1 = py * SCALE - 0.5f;
    s.valid = (xn0 > -2.0f) & (xn0 < 1024.0f) &
              (xn1 > -2.0f) & (xn1 < 1024.0f);
    float f0 = floorf(xn0);
    float f1 = floorf(xn1);
    float t0 = xn0 - f0;
    float t1 = xn1 - f1;
    int P0 = min(max((int)f0, -1), 1023);
    int P1 = min(max((int)f1, -1), 1023);
    bspline_w(t0, s.wA);
    bspline_w(t1, s.wB);
    s.q = (P0 + 1) * TD + (P1 + 1);
    return s;
}

__device__ __forceinline__ float eval_pt(const Pt& s, uint4 A, uint4 B) {
    float acc;
    acc = s.wA[0] * rowdot(A.x, A.y, s.wB);
    acc = fmaf(s.wA[1], rowdot(A.z, A.w, s.wB), acc);
    acc = fmaf(s.wA[2], rowdot(B.x, B.y, s.wB), acc);
    acc = fmaf(s.wA[3], rowdot(B.z, B.w, s.wB), acc);
    return s.valid ? acc : 0.0f;
}

__global__ __launch_bounds__(256) void spline_kernel(
    const float4* __restrict__ x,      // [N/2] two points per float4
    float2*       __restrict__ out)    // [N/2]
{
    int n2 = blockIdx.x * blockDim.x + threadIdx.x;
    float4 q = __ldcs(x + n2);

    Pt sA = setup_pt(q.x, q.y);
    Pt sB = setup_pt(q.z, q.w);

    const uint4* pA = (const uint4*)(g_patch + (size_t)sA.q * 16);
    const uint4* pB = (const uint4*)(g_patch + (size_t)sB.q * 16);
    uint4 A0 = __ldg(pA);
    uint4 A1 = __ldg(pA + 1);
    uint4 B0 = __ldg(pB);
    uint4 B1 = __ldg(pB + 1);

    float2 r;
    r.x = eval_pt(sA, A0, A1);
    r.y = eval_pt(sB, B0, B1);
    __stcs(out + n2, r);
}

extern "C" void kernel_launch(void* const* d_in, const int* in_sizes, int n_in,
                              void* d_out, int out_size) {
    const float* x      = (const float*)d_in[0];
    const float* coeffs = (const float*)d_in[1];
    float*       out    = (float*)d_out;

    const int nt = 256;
    build_patch<<<(NCELL + nt - 1) / nt, nt>>>(coeffs);
    spline_kernel<<<(NPTS / 2) / nt, nt>>>((const float4*)x, (float2*)out);
}